// round 8
// baseline (speedup 1.0000x reference)
#include <cuda_runtime.h>
#include <cuda_bf16.h>
#include <math.h>

// Problem constants
#define BB  2
#define SS  4096
#define HH  2048
#define NHH 8
#define DD  128
#define KDD 1024        // NH*D
#define WW  4
#define MM  (BB*SS)     // 8192
#define HALF_D 64
#define NCOMB (4 * KDD) // 4096 = 3KDD (qkv) + KDD (z)

// ---------------------------------------------------------------------------
// Device scratch
// ---------------------------------------------------------------------------
__device__ float g_qkv[(size_t)MM * 3 * KDD];
__device__ float g_z  [(size_t)MM * KDD];
__device__ float g_bg [(size_t)MM * NHH];
__device__ float g_ag [(size_t)MM * NHH];
__device__ float g_att[(size_t)MM * KDD];
__device__ float g_yn [(size_t)MM * KDD];       // tf32-rounded
__device__ float g_cos[(size_t)SS * HALF_D];
__device__ float g_sin[(size_t)SS * HALF_D];
__device__ float g_xr  [(size_t)MM * HH];       // tf32-rounded x
__device__ float g_Wcomb[(size_t)NCOMB * HH];   // [Wqkv^T | Wz^T] rounded
__device__ float g_Woutr[(size_t)HH * KDD];     // Wout^T rounded [HH][KDD]
__device__ float g_Wt  [16 * HH];               // transposed Wb|Wa

// ---------------------------------------------------------------------------
// helpers
// ---------------------------------------------------------------------------
__device__ __forceinline__ float f2tf32f(float x) {
    unsigned u;
    asm("cvt.rna.tf32.f32 %0, %1;" : "=r"(u) : "f"(x));
    return __uint_as_float(u);
}

__device__ __forceinline__ void mma_tf32(float c[4], const unsigned a[4],
                                         const unsigned b[2]) {
    asm volatile(
        "mma.sync.aligned.m16n8k8.row.col.f32.tf32.tf32.f32 "
        "{%0,%1,%2,%3}, {%4,%5,%6,%7}, {%8,%9}, {%0,%1,%2,%3};"
        : "+f"(c[0]), "+f"(c[1]), "+f"(c[2]), "+f"(c[3])
        : "r"(a[0]), "r"(a[1]), "r"(a[2]), "r"(a[3]), "r"(b[0]), "r"(b[1]));
}

__device__ __forceinline__ void ldsm_x4(unsigned& r0, unsigned& r1,
                                        unsigned& r2, unsigned& r3,
                                        unsigned addr) {
    asm volatile("ldmatrix.sync.aligned.m8n8.x4.shared.b16 {%0,%1,%2,%3}, [%4];"
                 : "=r"(r0), "=r"(r1), "=r"(r2), "=r"(r3) : "r"(addr));
}

__device__ __forceinline__ void cp_async16(void* smem, const void* gmem) {
    unsigned s = (unsigned)__cvta_generic_to_shared(smem);
    asm volatile("cp.async.cg.shared.global [%0], [%1], 16;\n" ::
                 "r"(s), "l"(gmem));
}
__device__ __forceinline__ void cp_commit() {
    asm volatile("cp.async.commit_group;\n");
}
template <int N>
__device__ __forceinline__ void cp_wait() {
    asm volatile("cp.async.wait_group %0;\n" :: "n"(N));
}

// ---------------------------------------------------------------------------
// tf32 rounding pass (float4)
// ---------------------------------------------------------------------------
__global__ void round_tf32_k(const float* __restrict__ src,
                             float* __restrict__ dst, int n4)
{
    int i = blockIdx.x * blockDim.x + threadIdx.x;
    if (i >= n4) return;
    float4 v = reinterpret_cast<const float4*>(src)[i];
    v.x = f2tf32f(v.x); v.y = f2tf32f(v.y);
    v.z = f2tf32f(v.z); v.w = f2tf32f(v.w);
    reinterpret_cast<float4*>(dst)[i] = v;
}

// ---------------------------------------------------------------------------
// Transpose + tf32 round: src[K][N] -> dst[N][K]
// ---------------------------------------------------------------------------
__global__ void transpose_round_k(const float* __restrict__ src,
                                  float* __restrict__ dst, int Kdim, int Ndim)
{
    __shared__ float t[32][33];
    int n0 = blockIdx.x * 32, k0 = blockIdx.y * 32;
    int tx = threadIdx.x, ty = threadIdx.y;
    #pragma unroll
    for (int i = 0; i < 4; i++)
        t[ty + i * 8][tx] =
            f2tf32f(src[(size_t)(k0 + ty + i * 8) * Ndim + n0 + tx]);
    __syncthreads();
    #pragma unroll
    for (int i = 0; i < 4; i++)
        dst[(size_t)(n0 + ty + i * 8) * Kdim + k0 + tx] = t[tx][ty + i * 8];
}

// ---------------------------------------------------------------------------
// TF32 GEMM: ldmatrix fragments, 3-stage cp.async ring, one barrier/iter.
// A row-major [M][K], Bt row-major [N][K], pre-rounded tf32.
// BM=128, BN=256, BK=32, 512 thr (16 warps 2x8), warp tile 64x32.
// MODE 0: C[M,N] plain.  MODE 1: combined qkv|z epilogue with fused RoPE.
// ---------------------------------------------------------------------------
#define TS_STRIDE 36
#define A_FLOATS (128 * TS_STRIDE)             // 4608
#define B_FLOATS (256 * TS_STRIDE)             // 9216
#define STAGE_FLOATS (A_FLOATS + B_FLOATS)     // 13824
#define STAGE_BYTES (STAGE_FLOATS * 4)         // 55296
#define NSTAGE 3
#define GTHREADS 512

template <int MODE>
__global__ __launch_bounds__(GTHREADS, 1) void gemm_tf32(
    const float* __restrict__ A, const float* __restrict__ Bt,
    float* __restrict__ C, int M, int N, int K)
{
    extern __shared__ float sm[];
    const unsigned smem_u32 = (unsigned)__cvta_generic_to_shared(sm);

    const int tid  = threadIdx.x;
    const int wid  = tid >> 5;
    const int lane = tid & 31;
    const int r4   = lane >> 2;
    const int lc   = lane & 3;

    const int row0 = blockIdx.y * 128;
    const int col0 = blockIdx.x * 256;
    const int warp_row = (wid >> 3) * 64;     // 0 or 64
    const int warp_col = (wid & 7) * 32;      // 0..224

    auto issue = [&](int k0, int st) {
        float* As = sm + st * STAGE_FLOATS;
        float* Bs = As + A_FLOATS;
        #pragma unroll
        for (int i = 0; i < 2; i++) {          // A: 1024 chunks
            int idx = tid + i * GTHREADS;
            int r = idx >> 3, c = (idx & 7) * 4;
            cp_async16(&As[r * TS_STRIDE + c],
                       &A[(size_t)(row0 + r) * K + k0 + c]);
        }
        #pragma unroll
        for (int i = 0; i < 4; i++) {          // B: 2048 chunks
            int idx = tid + i * GTHREADS;
            int r = idx >> 3, c = (idx & 7) * 4;
            cp_async16(&Bs[r * TS_STRIDE + c],
                       &Bt[(size_t)(col0 + r) * K + k0 + c]);
        }
        cp_commit();
    };

    const int lrow = lane & 15;
    const int lcolb = (lane & 16) ? 16 : 0;
    const unsigned a_lane = smem_u32 +
        (unsigned)((warp_row + lrow) * TS_STRIDE * 4) + lcolb;
    const unsigned b_lane = smem_u32 + A_FLOATS * 4 +
        (unsigned)((warp_col + lrow) * TS_STRIDE * 4) + lcolb;

    float c[4][4][4];
    #pragma unroll
    for (int i = 0; i < 4; i++)
        #pragma unroll
        for (int j = 0; j < 4; j++)
            #pragma unroll
            for (int t = 0; t < 4; t++) c[i][j][t] = 0.f;

    const int nk = K >> 5;
    issue(0, 0);
    issue(32, 1);

    #pragma unroll 1
    for (int t = 0; t < nk; t++) {
        if (t < nk - 1) cp_wait<1>(); else cp_wait<0>();
        __syncthreads();

        if (t + 2 < nk) issue((t + 2) << 5, (t + 2) % NSTAGE);

        const int cur = t % NSTAGE;
        const unsigned a_st = a_lane + cur * STAGE_BYTES;
        const unsigned b_st = b_lane + cur * STAGE_BYTES;
        #pragma unroll
        for (int kc = 0; kc < 4; kc++) {
            const unsigned koff = kc * 32;
            unsigned a[4][4], b[4][2];
            #pragma unroll
            for (int mt = 0; mt < 4; mt++)
                ldsm_x4(a[mt][0], a[mt][1], a[mt][2], a[mt][3],
                        a_st + (unsigned)(mt * 16 * TS_STRIDE * 4) + koff);
            #pragma unroll
            for (int np = 0; np < 2; np++)
                ldsm_x4(b[2*np][0], b[2*np+1][0], b[2*np][1], b[2*np+1][1],
                        b_st + (unsigned)(np * 16 * TS_STRIDE * 4) + koff);
            #pragma unroll
            for (int mt = 0; mt < 4; mt++)
                #pragma unroll
                for (int nt = 0; nt < 4; nt++)
                    mma_tf32(c[mt][nt], a[mt], b[nt]);
        }
    }

    #pragma unroll
    for (int mt = 0; mt < 4; mt++) {
        #pragma unroll
        for (int nt = 0; nt < 4; nt++) {
            int rg = row0 + warp_row + mt * 16 + r4;
            int cg = col0 + warp_col + nt * 8 + 2 * lc;
            float v0 = c[mt][nt][0], v1 = c[mt][nt][1];
            float v2 = c[mt][nt][2], v3 = c[mt][nt][3];
            if (MODE == 1) {
                if (cg < 2 * KDD) {
                    int p = (cg & (DD - 1)) >> 1;
                    int pos0 = rg & (SS - 1);
                    int pos1 = (rg + 8) & (SS - 1);
                    float c0 = g_cos[pos0 * HALF_D + p], s0 = g_sin[pos0 * HALF_D + p];
                    float c1 = g_cos[pos1 * HALF_D + p], s1 = g_sin[pos1 * HALF_D + p];
                    float o0 = v0 * c0 - v1 * s0, o1 = v0 * s0 + v1 * c0;
                    float o2 = v2 * c1 - v3 * s1, o3 = v2 * s1 + v3 * c1;
                    v0 = o0; v1 = o1; v2 = o2; v3 = o3;
                }
                if (cg < 3 * KDD) {
                    *reinterpret_cast<float2*>(
                        &g_qkv[(size_t)rg * (3 * KDD) + cg]) = make_float2(v0, v1);
                    *reinterpret_cast<float2*>(
                        &g_qkv[(size_t)(rg + 8) * (3 * KDD) + cg]) = make_float2(v2, v3);
                } else {
                    int cz = cg - 3 * KDD;
                    *reinterpret_cast<float2*>(
                        &g_z[(size_t)rg * KDD + cz]) = make_float2(v0, v1);
                    *reinterpret_cast<float2*>(
                        &g_z[(size_t)(rg + 8) * KDD + cz]) = make_float2(v2, v3);
                }
            } else {
                *reinterpret_cast<float2*>(&C[(size_t)rg * N + cg]) =
                    make_float2(v0, v1);
                *reinterpret_cast<float2*>(&C[(size_t)(rg + 8) * N + cg]) =
                    make_float2(v2, v3);
            }
        }
    }
}

// ---------------------------------------------------------------------------
// Transpose Wb|Wa (HHx8 each) into g_Wt[16][HH]
// ---------------------------------------------------------------------------
__global__ void transpose_gates_k(const float* __restrict__ Wb,
                                  const float* __restrict__ Wa)
{
    int idx = blockIdx.x * blockDim.x + threadIdx.x;
    if (idx >= 16 * HH) return;
    int n = idx / HH, k = idx % HH;
    g_Wt[idx] = (n < 8) ? Wb[(size_t)k * NHH + n]
                        : Wa[(size_t)k * NHH + (n - 8)];
}

// ---------------------------------------------------------------------------
// Gate projections: one block (512 thr) per row; warp n computes output n.
// ---------------------------------------------------------------------------
__global__ __launch_bounds__(512) void proj_gates2(const float* __restrict__ x)
{
    __shared__ float xs[HH];
    const int row = blockIdx.x;
    reinterpret_cast<float4*>(xs)[threadIdx.x] =
        reinterpret_cast<const float4*>(x + (size_t)row * HH)[threadIdx.x];
    __syncthreads();

    const int w = threadIdx.x >> 5, lane = threadIdx.x & 31;
    const float* wt = g_Wt + w * HH;
    float s = 0.f;
    #pragma unroll
    for (int it = 0; it < HH / 128; it++) {
        int k = it * 128 + lane * 4;
        float4 xv = *reinterpret_cast<const float4*>(&xs[k]);
        float4 wv = *reinterpret_cast<const float4*>(&wt[k]);
        s += xv.x * wv.x + xv.y * wv.y + xv.z * wv.z + xv.w * wv.w;
    }
    #pragma unroll
    for (int o = 16; o > 0; o >>= 1) s += __shfl_down_sync(0xffffffffu, s, o);
    if (lane == 0) {
        if (w < 8) g_bg[(size_t)row * NHH + w] = s;
        else       g_ag[(size_t)row * NHH + (w - 8)] = s;
    }
}

// ---------------------------------------------------------------------------
// RoPE tables (fp32 angle, double inv-freq)
// ---------------------------------------------------------------------------
__global__ void rope_tables_k()
{
    int idx = blockIdx.x * blockDim.x + threadIdx.x;
    if (idx >= SS * HALF_D) return;
    int pos = idx / HALF_D, i = idx % HALF_D;
    float inv = (float)exp(-((double)(2 * i) / (double)DD) * log(1.0e6));
    float ang = (float)pos * inv;
    float s, c;
    sincosf(ang, &s, &c);
    g_cos[idx] = c;
    g_sin[idx] = s;
}

// ---------------------------------------------------------------------------
// Tiled sliding-window gated attention
// ---------------------------------------------------------------------------
#define ATS 32
__global__ __launch_bounds__(256) void attn2_k()
{
    __shared__ float ks[36 * DD];
    __shared__ float vs[36 * DD];
    __shared__ float bgs[36];
    __shared__ float ags[ATS];

    const int s_base = blockIdx.x * ATS;
    const int h = blockIdx.y, b = blockIdx.z;
    const int tid = threadIdx.x;
    const int wid = tid >> 5, lane = tid & 31;

    for (int t = tid; t < 36 * 32; t += 256) {
        int li = t >> 5, c4 = (t & 31) * 4;
        int j = s_base - 4 + li;
        float4 kv = make_float4(0.f, 0.f, 0.f, 0.f), vv = kv;
        if (j >= 0) {
            size_t r = (size_t)(b * SS + j) * (3 * KDD) + h * DD + c4;
            kv = *reinterpret_cast<const float4*>(&g_qkv[r + KDD]);
            vv = *reinterpret_cast<const float4*>(&g_qkv[r + 2 * KDD]);
        }
        *reinterpret_cast<float4*>(&ks[li * DD + c4]) = kv;
        *reinterpret_cast<float4*>(&vs[li * DD + c4]) = vv;
    }
    if (tid < 36) {
        int j = s_base - 4 + tid;
        bgs[tid] = (j >= 0) ? g_bg[(size_t)(b * SS + j) * NHH + h] : 0.f;
    }
    if (tid >= 64 && tid < 64 + ATS)
        ags[tid - 64] = g_ag[(size_t)(b * SS + s_base + tid - 64) * NHH + h];
    __syncthreads();

    const float scale = 0.08838834764831845f;

    #pragma unroll
    for (int i = 0; i < 4; i++) {
        const int sl = wid + 8 * i;
        const int s  = s_base + sl;
        const size_t orow = (size_t)(b * SS + s) * KDD + h * DD + lane * 4;

        if (s == 0) {
            *reinterpret_cast<float4*>(&g_att[orow]) =
                *reinterpret_cast<const float4*>(&vs[4 * DD + lane * 4]);
            continue;
        }

        const float4 q4 = *reinterpret_cast<const float4*>(
            &g_qkv[(size_t)(b * SS + s) * (3 * KDD) + h * DD + lane * 4]);
        const float agv = ags[sl];
        float4 acc = make_float4(0.f, 0.f, 0.f, 0.f);

        #pragma unroll
        for (int off = 0; off <= WW; off++) {
            if (s - off < 0) continue;
            const int li = sl + 4 - off;
            const float4 k4 = *reinterpret_cast<const float4*>(
                &ks[li * DD + lane * 4]);
            float part = q4.x * k4.x + q4.y * k4.y + q4.z * k4.z + q4.w * k4.w;
            #pragma unroll
            for (int o = 16; o > 0; o >>= 1)
                part += __shfl_xor_sync(0xffffffffu, part, o);
            const float gate = 1.f / (1.f + expf(-agv * bgs[li]));
            const float wgt = part * scale * gate;
            const float4 v4 = *reinterpret_cast<const float4*>(
                &vs[li * DD + lane * 4]);
            acc.x += wgt * v4.x; acc.y += wgt * v4.y;
            acc.z += wgt * v4.z; acc.w += wgt * v4.w;
        }
        *reinterpret_cast<float4*>(&g_att[orow]) = acc;
    }
}

// ---------------------------------------------------------------------------
// Gated RMS norm (emits tf32-rounded yn)
// ---------------------------------------------------------------------------
__global__ __launch_bounds__(256) void norm_k(const float* __restrict__ nw)
{
    const int row = blockIdx.x, tid = threadIdx.x;
    const size_t base = (size_t)row * KDD;

    float y[4], zz[4];
    float ss = 0.f;
    #pragma unroll
    for (int i = 0; i < 4; i++) {
        int c   = tid + i * 256;
        float zv  = g_z[base + c];
        float sig = 1.f / (1.f + expf(-zv));
        float yv  = g_att[base + c] * sig;
        y[i]  = yv;
        zz[i] = zv * sig;
        ss   += yv * yv;
    }
    __shared__ float red[8];
    #pragma unroll
    for (int o = 16; o > 0; o >>= 1) ss += __shfl_down_sync(0xffffffffu, ss, o);
    if ((tid & 31) == 0) red[tid >> 5] = ss;
    __syncthreads();
    if (tid < 8) {
        float v = red[tid];
        #pragma unroll
        for (int o = 4; o > 0; o >>= 1) v += __shfl_down_sync(0xffu, v, o);
        if (tid == 0) red[0] = v;
    }
    __syncthreads();
    const float rinv = rsqrtf(red[0] / (float)KDD + 1e-6f);

    #pragma unroll
    for (int i = 0; i < 4; i++) {
        int c = tid + i * 256;
        g_yn[base + c] = f2tf32f(y[i] * rinv * nw[c] * zz[i]);
    }
}

// ---------------------------------------------------------------------------
// Launch
// ---------------------------------------------------------------------------
extern "C" void kernel_launch(void* const* d_in, const int* in_sizes, int n_in,
                              void* d_out, int out_size)
{
    const float* x    = (const float*)d_in[0];
    const float* Wqkv = (const float*)d_in[1];
    const float* Wz   = (const float*)d_in[2];
    const float* Wb   = (const float*)d_in[3];
    const float* Wa   = (const float*)d_in[4];
    const float* nw   = (const float*)d_in[5];
    const float* Wout = (const float*)d_in[6];
    float* out = (float*)d_out;

    float *p_xr, *p_Wcomb, *p_Woutr, *p_yn;
    cudaGetSymbolAddress((void**)&p_xr,    g_xr);
    cudaGetSymbolAddress((void**)&p_Wcomb, g_Wcomb);
    cudaGetSymbolAddress((void**)&p_Woutr, g_Woutr);
    cudaGetSymbolAddress((void**)&p_yn,    g_yn);

    const int smem_bytes = NSTAGE * STAGE_BYTES;   // 165888
    static bool attr_set = false;
    if (!attr_set) {
        cudaFuncSetAttribute(gemm_tf32<0>,
            cudaFuncAttributeMaxDynamicSharedMemorySize, smem_bytes);
        cudaFuncSetAttribute(gemm_tf32<1>,
            cudaFuncAttributeMaxDynamicSharedMemorySize, smem_bytes);
        attr_set = true;
    }

    // 1) Round x; transpose+round weights; rope tables; gate transpose
    {
        int n = MM * HH / 4;
        round_tf32_k<<<(n + 255) / 256, 256>>>(x, p_xr, n);
        dim3 blk(32, 8);
        transpose_round_k<<<dim3(3 * KDD / 32, HH / 32), blk>>>(
            Wqkv, p_Wcomb, HH, 3 * KDD);
        transpose_round_k<<<dim3(KDD / 32, HH / 32), blk>>>(
            Wz, p_Wcomb + (size_t)3 * KDD * HH, HH, KDD);
        transpose_round_k<<<dim3(HH / 32, KDD / 32), blk>>>(
            Wout, p_Woutr, KDD, HH);
        int t = SS * HALF_D;
        rope_tables_k<<<(t + 255) / 256, 256>>>();
        int m = 16 * HH;
        transpose_gates_k<<<(m + 255) / 256, 256>>>(Wb, Wa);
    }

    // 2) Combined qkv|z projection (RoPE fused)
    {
        dim3 g(NCOMB / 256, MM / 128);
        gemm_tf32<1><<<g, GTHREADS, smem_bytes>>>(p_xr, p_Wcomb, nullptr,
                                                  MM, NCOMB, HH);
    }

    // 3) Gate projections
    proj_gates2<<<MM, 512>>>(x);

    // 4) Tiled sliding-window gated attention
    {
        dim3 g(SS / ATS, NHH, BB);
        attn2_k<<<g, 256>>>();
    }

    // 5) Gated RMS norm
    norm_k<<<MM, 256>>>(nw);

    // 6) Output projection
    {
        dim3 g(HH / 256, MM / 128);
        gemm_tf32<0><<<g, GTHREADS, smem_bytes>>>(p_yn, p_Woutr, out,
                                                  MM, HH, KDD);
    }
}

// round 11
// speedup vs baseline: 1.1417x; 1.1417x over previous
#include <cuda_runtime.h>
#include <cuda_fp16.h>
#include <math.h>

// Problem constants
#define BB  2
#define SS  4096
#define HH  2048
#define NHH 8
#define DD  128
#define KDD 1024        // NH*D
#define WW  4
#define MM  (BB*SS)     // 8192
#define HALF_D 64
#define NCOMB (4 * KDD) // 4096 = 3KDD (qkv) + KDD (z)

// ---------------------------------------------------------------------------
// Device scratch
// ---------------------------------------------------------------------------
__device__ float g_qkv[(size_t)MM * 3 * KDD];
__device__ float g_z  [(size_t)MM * KDD];
__device__ float g_bg [(size_t)MM * NHH];
__device__ float g_ag [(size_t)MM * NHH];
__device__ float g_att[(size_t)MM * KDD];
__device__ float g_cos[(size_t)SS * HALF_D];
__device__ float g_sin[(size_t)SS * HALF_D];
__device__ __half g_xh  [(size_t)MM * HH];      // fp16 x
__device__ __half g_Wch [(size_t)NCOMB * HH];   // [Wqkv^T | Wz^T] fp16
__device__ __half g_Wouth[(size_t)HH * KDD];    // Wout^T fp16 [HH][KDD]
__device__ __half g_ynh [(size_t)MM * KDD];     // fp16 normed y
__device__ float g_Wt  [16 * HH];               // transposed Wb|Wa

// ---------------------------------------------------------------------------
// helpers
// ---------------------------------------------------------------------------
__device__ __forceinline__ void mma_f16(float c[4], const unsigned a[4],
                                        const unsigned b[2]) {
    asm volatile(
        "mma.sync.aligned.m16n8k16.row.col.f32.f16.f16.f32 "
        "{%0,%1,%2,%3}, {%4,%5,%6,%7}, {%8,%9}, {%0,%1,%2,%3};"
        : "+f"(c[0]), "+f"(c[1]), "+f"(c[2]), "+f"(c[3])
        : "r"(a[0]), "r"(a[1]), "r"(a[2]), "r"(a[3]), "r"(b[0]), "r"(b[1]));
}

__device__ __forceinline__ void ldsm_x4(unsigned& r0, unsigned& r1,
                                        unsigned& r2, unsigned& r3,
                                        unsigned addr) {
    asm volatile("ldmatrix.sync.aligned.m8n8.x4.shared.b16 {%0,%1,%2,%3}, [%4];"
                 : "=r"(r0), "=r"(r1), "=r"(r2), "=r"(r3) : "r"(addr));
}

__device__ __forceinline__ void cp_async16(void* smem, const void* gmem) {
    unsigned s = (unsigned)__cvta_generic_to_shared(smem);
    asm volatile("cp.async.cg.shared.global [%0], [%1], 16;\n" ::
                 "r"(s), "l"(gmem));
}
__device__ __forceinline__ void cp_commit() {
    asm volatile("cp.async.commit_group;\n");
}
template <int N>
__device__ __forceinline__ void cp_wait() {
    asm volatile("cp.async.wait_group %0;\n" :: "n"(N));
}

// ---------------------------------------------------------------------------
// fp16 rounding pass: 4 floats -> 4 halfs per thread
// ---------------------------------------------------------------------------
__global__ void round_f16_k(const float* __restrict__ src,
                            __half* __restrict__ dst, int n4)
{
    int i = blockIdx.x * blockDim.x + threadIdx.x;
    if (i >= n4) return;
    float4 v = reinterpret_cast<const float4*>(src)[i];
    __half2 h0 = __floats2half2_rn(v.x, v.y);
    __half2 h1 = __floats2half2_rn(v.z, v.w);
    __half2* d = reinterpret_cast<__half2*>(dst + (size_t)i * 4);
    d[0] = h0;
    d[1] = h1;
}

// ---------------------------------------------------------------------------
// Transpose + fp16 round: src[K][N] fp32 -> dst[N][K] fp16
// ---------------------------------------------------------------------------
__global__ void transpose_f16_k(const float* __restrict__ src,
                                __half* __restrict__ dst, int Kdim, int Ndim)
{
    __shared__ float t[32][33];
    int n0 = blockIdx.x * 32, k0 = blockIdx.y * 32;
    int tx = threadIdx.x, ty = threadIdx.y;
    #pragma unroll
    for (int i = 0; i < 4; i++)
        t[ty + i * 8][tx] =
            src[(size_t)(k0 + ty + i * 8) * Ndim + n0 + tx];
    __syncthreads();
    #pragma unroll
    for (int i = 0; i < 4; i++)
        dst[(size_t)(n0 + ty + i * 8) * Kdim + k0 + tx] =
            __float2half_rn(t[tx][ty + i * 8]);
}

// ---------------------------------------------------------------------------
// FP16 GEMM: ldmatrix fragments, 3-stage cp.async ring, one barrier/iter.
// A row-major [M][K] fp16, Bt row-major [N][K] fp16, fp32 accum/output.
// BM=BN=128, BK=64 (=128B rows), 256 thr (8 warps 2x4), warp tile 64x32.
// MODE 0: C[M,N] plain.  MODE 1: combined qkv|z epilogue with fused RoPE.
// ---------------------------------------------------------------------------
#define TSH 72                                 // halfs per smem row (144 B)
#define TILE_H (128 * TSH)                     // 9216 halfs
#define STAGE_H (2 * TILE_H)                   // A + B
#define STAGE_BYTES (STAGE_H * 2)              // 36864
#define NSTAGE 3

template <int MODE>
__global__ __launch_bounds__(256, 2) void gemm_f16(
    const __half* __restrict__ A, const __half* __restrict__ Bt,
    float* __restrict__ C, int M, int N, int K)
{
    extern __shared__ __half sm[];
    const unsigned smem_u32 = (unsigned)__cvta_generic_to_shared(sm);

    const int tid  = threadIdx.x;
    const int wid  = tid >> 5;
    const int lane = tid & 31;
    const int r4   = lane >> 2;
    const int lc   = lane & 3;

    const int row0 = blockIdx.y * 128;
    const int col0 = blockIdx.x * 128;
    const int warp_row = (wid >> 2) * 64;
    const int warp_col = (wid & 3) * 32;

    auto issue = [&](int k0, int st) {
        __half* As = sm + st * STAGE_H;
        __half* Bs = As + TILE_H;
        #pragma unroll
        for (int i = 0; i < 4; i++) {          // 1024 chunks each for A and B
            int idx = tid + i * 256;
            int r = idx >> 3, ch = idx & 7;    // row, 16B-chunk (8 halfs)
            cp_async16(&As[r * TSH + ch * 8],
                       &A[(size_t)(row0 + r) * K + k0 + ch * 8]);
            cp_async16(&Bs[r * TSH + ch * 8],
                       &Bt[(size_t)(col0 + r) * K + k0 + ch * 8]);
        }
        cp_commit();
    };

    const int lrow = lane & 15;
    const int lcolb = (lane & 16) ? 16 : 0;    // byte offset (8 halfs)
    const unsigned a_lane = smem_u32 +
        (unsigned)((warp_row + lrow) * TSH * 2) + lcolb;
    const unsigned b_lane = smem_u32 + TILE_H * 2 +
        (unsigned)((warp_col + lrow) * TSH * 2) + lcolb;

    float c[4][4][4];
    #pragma unroll
    for (int i = 0; i < 4; i++)
        #pragma unroll
        for (int j = 0; j < 4; j++)
            #pragma unroll
            for (int t = 0; t < 4; t++) c[i][j][t] = 0.f;

    const int nk = K >> 6;                     // BK = 64
    issue(0, 0);
    issue(64, 1);

    #pragma unroll 1
    for (int t = 0; t < nk; t++) {
        if (t < nk - 1) cp_wait<1>(); else cp_wait<0>();
        __syncthreads();

        if (t + 2 < nk) issue((t + 2) << 6, (t + 2) % NSTAGE);

        const int cur = t % NSTAGE;
        const unsigned a_st = a_lane + cur * STAGE_BYTES;
        const unsigned b_st = b_lane + cur * STAGE_BYTES;
        #pragma unroll
        for (int kc = 0; kc < 4; kc++) {       // k16 per chunk
            const unsigned koff = kc * 32;     // 16 halfs = 32 bytes
            unsigned a[4][4], b[4][2];
            #pragma unroll
            for (int mt = 0; mt < 4; mt++)
                ldsm_x4(a[mt][0], a[mt][1], a[mt][2], a[mt][3],
                        a_st + (unsigned)(mt * 16 * TSH * 2) + koff);
            #pragma unroll
            for (int np = 0; np < 2; np++)
                ldsm_x4(b[2*np][0], b[2*np+1][0], b[2*np][1], b[2*np+1][1],
                        b_st + (unsigned)(np * 16 * TSH * 2) + koff);
            #pragma unroll
            for (int mt = 0; mt < 4; mt++)
                #pragma unroll
                for (int nt = 0; nt < 4; nt++)
                    mma_f16(c[mt][nt], a[mt], b[nt]);
        }
    }

    #pragma unroll
    for (int mt = 0; mt < 4; mt++) {
        #pragma unroll
        for (int nt = 0; nt < 4; nt++) {
            int rg = row0 + warp_row + mt * 16 + r4;
            int cg = col0 + warp_col + nt * 8 + 2 * lc;
            float v0 = c[mt][nt][0], v1 = c[mt][nt][1];
            float v2 = c[mt][nt][2], v3 = c[mt][nt][3];
            if (MODE == 1) {
                if (cg < 2 * KDD) {
                    int p = (cg & (DD - 1)) >> 1;
                    int pos0 = rg & (SS - 1);
                    int pos1 = (rg + 8) & (SS - 1);
                    float c0 = g_cos[pos0 * HALF_D + p], s0 = g_sin[pos0 * HALF_D + p];
                    float c1 = g_cos[pos1 * HALF_D + p], s1 = g_sin[pos1 * HALF_D + p];
                    float o0 = v0 * c0 - v1 * s0, o1 = v0 * s0 + v1 * c0;
                    float o2 = v2 * c1 - v3 * s1, o3 = v2 * s1 + v3 * c1;
                    v0 = o0; v1 = o1; v2 = o2; v3 = o3;
                }
                if (cg < 3 * KDD) {
                    *reinterpret_cast<float2*>(
                        &g_qkv[(size_t)rg * (3 * KDD) + cg]) = make_float2(v0, v1);
                    *reinterpret_cast<float2*>(
                        &g_qkv[(size_t)(rg + 8) * (3 * KDD) + cg]) = make_float2(v2, v3);
                } else {
                    int cz = cg - 3 * KDD;
                    *reinterpret_cast<float2*>(
                        &g_z[(size_t)rg * KDD + cz]) = make_float2(v0, v1);
                    *reinterpret_cast<float2*>(
                        &g_z[(size_t)(rg + 8) * KDD + cz]) = make_float2(v2, v3);
                }
            } else {
                *reinterpret_cast<float2*>(&C[(size_t)rg * N + cg]) =
                    make_float2(v0, v1);
                *reinterpret_cast<float2*>(&C[(size_t)(rg + 8) * N + cg]) =
                    make_float2(v2, v3);
            }
        }
    }
}

// ---------------------------------------------------------------------------
// Transpose Wb|Wa (HHx8 each) into g_Wt[16][HH]
// ---------------------------------------------------------------------------
__global__ void transpose_gates_k(const float* __restrict__ Wb,
                                  const float* __restrict__ Wa)
{
    int idx = blockIdx.x * blockDim.x + threadIdx.x;
    if (idx >= 16 * HH) return;
    int n = idx / HH, k = idx % HH;
    g_Wt[idx] = (n < 8) ? Wb[(size_t)k * NHH + n]
                        : Wa[(size_t)k * NHH + (n - 8)];
}

// ---------------------------------------------------------------------------
// Gate projections: one block (512 thr) per row; warp n computes output n.
// ---------------------------------------------------------------------------
__global__ __launch_bounds__(512) void proj_gates2(const float* __restrict__ x)
{
    __shared__ float xs[HH];
    const int row = blockIdx.x;
    reinterpret_cast<float4*>(xs)[threadIdx.x] =
        reinterpret_cast<const float4*>(x + (size_t)row * HH)[threadIdx.x];
    __syncthreads();

    const int w = threadIdx.x >> 5, lane = threadIdx.x & 31;
    const float* wt = g_Wt + w * HH;
    float s = 0.f;
    #pragma unroll
    for (int it = 0; it < HH / 128; it++) {
        int k = it * 128 + lane * 4;
        float4 xv = *reinterpret_cast<const float4*>(&xs[k]);
        float4 wv = *reinterpret_cast<const float4*>(&wt[k]);
        s += xv.x * wv.x + xv.y * wv.y + xv.z * wv.z + xv.w * wv.w;
    }
    #pragma unroll
    for (int o = 16; o > 0; o >>= 1) s += __shfl_down_sync(0xffffffffu, s, o);
    if (lane == 0) {
        if (w < 8) g_bg[(size_t)row * NHH + w] = s;
        else       g_ag[(size_t)row * NHH + (w - 8)] = s;
    }
}

// ---------------------------------------------------------------------------
// RoPE tables (fp32 angle, double inv-freq)
// ---------------------------------------------------------------------------
__global__ void rope_tables_k()
{
    int idx = blockIdx.x * blockDim.x + threadIdx.x;
    if (idx >= SS * HALF_D) return;
    int pos = idx / HALF_D, i = idx % HALF_D;
    float inv = (float)exp(-((double)(2 * i) / (double)DD) * log(1.0e6));
    float ang = (float)pos * inv;
    float s, c;
    sincosf(ang, &s, &c);
    g_cos[idx] = c;
    g_sin[idx] = s;
}

// ---------------------------------------------------------------------------
// Tiled sliding-window gated attention
// ---------------------------------------------------------------------------
#define ATS 32
__global__ __launch_bounds__(256) void attn2_k()
{
    __shared__ float ks[36 * DD];
    __shared__ float vs[36 * DD];
    __shared__ float bgs[36];
    __shared__ float ags[ATS];

    const int s_base = blockIdx.x * ATS;
    const int h = blockIdx.y, b = blockIdx.z;
    const int tid = threadIdx.x;
    const int wid = tid >> 5, lane = tid & 31;

    for (int t = tid; t < 36 * 32; t += 256) {
        int li = t >> 5, c4 = (t & 31) * 4;
        int j = s_base - 4 + li;
        float4 kv = make_float4(0.f, 0.f, 0.f, 0.f), vv = kv;
        if (j >= 0) {
            size_t r = (size_t)(b * SS + j) * (3 * KDD) + h * DD + c4;
            kv = *reinterpret_cast<const float4*>(&g_qkv[r + KDD]);
            vv = *reinterpret_cast<const float4*>(&g_qkv[r + 2 * KDD]);
        }
        *reinterpret_cast<float4*>(&ks[li * DD + c4]) = kv;
        *reinterpret_cast<float4*>(&vs[li * DD + c4]) = vv;
    }
    if (tid < 36) {
        int j = s_base - 4 + tid;
        bgs[tid] = (j >= 0) ? g_bg[(size_t)(b * SS + j) * NHH + h] : 0.f;
    }
    if (tid >= 64 && tid < 64 + ATS)
        ags[tid - 64] = g_ag[(size_t)(b * SS + s_base + tid - 64) * NHH + h];
    __syncthreads();

    const float scale = 0.08838834764831845f;

    #pragma unroll
    for (int i = 0; i < 4; i++) {
        const int sl = wid + 8 * i;
        const int s  = s_base + sl;
        const size_t orow = (size_t)(b * SS + s) * KDD + h * DD + lane * 4;

        if (s == 0) {
            *reinterpret_cast<float4*>(&g_att[orow]) =
                *reinterpret_cast<const float4*>(&vs[4 * DD + lane * 4]);
            continue;
        }

        const float4 q4 = *reinterpret_cast<const float4*>(
            &g_qkv[(size_t)(b * SS + s) * (3 * KDD) + h * DD + lane * 4]);
        const float agv = ags[sl];
        float4 acc = make_float4(0.f, 0.f, 0.f, 0.f);

        #pragma unroll
        for (int off = 0; off <= WW; off++) {
            if (s - off < 0) continue;
            const int li = sl + 4 - off;
            const float4 k4 = *reinterpret_cast<const float4*>(
                &ks[li * DD + lane * 4]);
            float part = q4.x * k4.x + q4.y * k4.y + q4.z * k4.z + q4.w * k4.w;
            #pragma unroll
            for (int o = 16; o > 0; o >>= 1)
                part += __shfl_xor_sync(0xffffffffu, part, o);
            const float gate = 1.f / (1.f + expf(-agv * bgs[li]));
            const float wgt = part * scale * gate;
            const float4 v4 = *reinterpret_cast<const float4*>(
                &vs[li * DD + lane * 4]);
            acc.x += wgt * v4.x; acc.y += wgt * v4.y;
            acc.z += wgt * v4.z; acc.w += wgt * v4.w;
        }
        *reinterpret_cast<float4*>(&g_att[orow]) = acc;
    }
}

// ---------------------------------------------------------------------------
// Gated RMS norm (emits fp16 yn)
// ---------------------------------------------------------------------------
__global__ __launch_bounds__(256) void norm_k(const float* __restrict__ nw)
{
    const int row = blockIdx.x, tid = threadIdx.x;
    const size_t base = (size_t)row * KDD;

    float y[4], zz[4];
    float ss = 0.f;
    #pragma unroll
    for (int i = 0; i < 4; i++) {
        int c   = tid + i * 256;
        float zv  = g_z[base + c];
        float sig = 1.f / (1.f + expf(-zv));
        float yv  = g_att[base + c] * sig;
        y[i]  = yv;
        zz[i] = zv * sig;
        ss   += yv * yv;
    }
    __shared__ float red[8];
    #pragma unroll
    for (int o = 16; o > 0; o >>= 1) ss += __shfl_down_sync(0xffffffffu, ss, o);
    if ((tid & 31) == 0) red[tid >> 5] = ss;
    __syncthreads();
    if (tid < 8) {
        float v = red[tid];
        #pragma unroll
        for (int o = 4; o > 0; o >>= 1) v += __shfl_down_sync(0xffu, v, o);
        if (tid == 0) red[0] = v;
    }
    __syncthreads();
    const float rinv = rsqrtf(red[0] / (float)KDD + 1e-6f);

    #pragma unroll
    for (int i = 0; i < 4; i++) {
        int c = tid + i * 256;
        g_ynh[base + c] = __float2half_rn(y[i] * rinv * nw[c] * zz[i]);
    }
}

// ---------------------------------------------------------------------------
// Launch
// ---------------------------------------------------------------------------
extern "C" void kernel_launch(void* const* d_in, const int* in_sizes, int n_in,
                              void* d_out, int out_size)
{
    const float* x    = (const float*)d_in[0];
    const float* Wqkv = (const float*)d_in[1];
    const float* Wz   = (const float*)d_in[2];
    const float* Wb   = (const float*)d_in[3];
    const float* Wa   = (const float*)d_in[4];
    const float* nw   = (const float*)d_in[5];
    const float* Wout = (const float*)d_in[6];
    float* out = (float*)d_out;

    __half *p_xh, *p_Wch, *p_Wouth, *p_ynh;
    cudaGetSymbolAddress((void**)&p_xh,    g_xh);
    cudaGetSymbolAddress((void**)&p_Wch,   g_Wch);
    cudaGetSymbolAddress((void**)&p_Wouth, g_Wouth);
    cudaGetSymbolAddress((void**)&p_ynh,   g_ynh);

    const int smem_bytes = NSTAGE * STAGE_BYTES;   // 110592
    static bool attr_set = false;
    if (!attr_set) {
        cudaFuncSetAttribute(gemm_f16<0>,
            cudaFuncAttributeMaxDynamicSharedMemorySize, smem_bytes);
        cudaFuncSetAttribute(gemm_f16<1>,
            cudaFuncAttributeMaxDynamicSharedMemorySize, smem_bytes);
        attr_set = true;
    }

    // 1) Round x to fp16; transpose weights to fp16; rope tables; gate W^T
    {
        int n = MM * HH / 4;
        round_f16_k<<<(n + 255) / 256, 256>>>(x, p_xh, n);
        dim3 blk(32, 8);
        transpose_f16_k<<<dim3(3 * KDD / 32, HH / 32), blk>>>(
            Wqkv, p_Wch, HH, 3 * KDD);
        transpose_f16_k<<<dim3(KDD / 32, HH / 32), blk>>>(
            Wz, p_Wch + (size_t)3 * KDD * HH, HH, KDD);
        transpose_f16_k<<<dim3(HH / 32, KDD / 32), blk>>>(
            Wout, p_Wouth, KDD, HH);
        int t = SS * HALF_D;
        rope_tables_k<<<(t + 255) / 256, 256>>>();
        int m = 16 * HH;
        transpose_gates_k<<<(m + 255) / 256, 256>>>(Wb, Wa);
    }

    // 2) Combined qkv|z projection (fp16 tensor cores, RoPE fused)
    {
        dim3 g(NCOMB / 128, MM / 128);
        gemm_f16<1><<<g, 256, smem_bytes>>>(p_xh, p_Wch, nullptr,
                                            MM, NCOMB, HH);
    }

    // 3) Gate projections
    proj_gates2<<<MM, 512>>>(x);

    // 4) Tiled sliding-window gated attention
    {
        dim3 g(SS / ATS, NHH, BB);
        attn2_k<<<g, 256>>>();
    }

    // 5) Gated RMS norm (fp16 output)
    norm_k<<<MM, 256>>>(nw);

    // 6) Output projection (fp16 tensor cores)
    {
        dim3 g(HH / 128, MM / 128);
        gemm_f16<0><<<g, 256, smem_bytes>>>(p_ynh, p_Wouth, out, MM, HH, KDD);
    }
}

// round 14
// speedup vs baseline: 1.6697x; 1.4625x over previous
#include <cuda_runtime.h>
#include <cuda_fp16.h>
#include <math.h>

// Problem constants
#define BB  2
#define SS  4096
#define HH  2048
#define NHH 8
#define DD  128
#define KDD 1024        // NH*D
#define WW  4
#define MM  (BB*SS)     // 8192
#define HALF_D 64
#define NCOMB (4 * KDD) // 4096 = 3KDD (qkv) + KDD (z)

// ---------------------------------------------------------------------------
// Device scratch
// ---------------------------------------------------------------------------
__device__ float g_qkv[(size_t)MM * 3 * KDD];
__device__ float g_z  [(size_t)MM * KDD];
__device__ float g_bg [(size_t)MM * NHH];
__device__ float g_ag [(size_t)MM * NHH];
__device__ float g_att[(size_t)MM * KDD];
__device__ float g_cos[(size_t)SS * HALF_D];
__device__ float g_sin[(size_t)SS * HALF_D];
__device__ __half g_xh  [(size_t)MM * HH];      // fp16 x
__device__ __half g_Wch [(size_t)NCOMB * HH];   // [Wqkv^T | Wz^T] fp16
__device__ __half g_Wouth[(size_t)HH * KDD];    // Wout^T fp16 [HH][KDD]
__device__ __half g_ynh [(size_t)MM * KDD];     // fp16 normed y
__device__ float g_Wt  [16 * HH];               // transposed Wb|Wa

// ---------------------------------------------------------------------------
// helpers
// ---------------------------------------------------------------------------
__device__ __forceinline__ void mma_f16(float c[4], const unsigned a[4],
                                        const unsigned b[2]) {
    asm volatile(
        "mma.sync.aligned.m16n8k16.row.col.f32.f16.f16.f32 "
        "{%0,%1,%2,%3}, {%4,%5,%6,%7}, {%8,%9}, {%0,%1,%2,%3};"
        : "+f"(c[0]), "+f"(c[1]), "+f"(c[2]), "+f"(c[3])
        : "r"(a[0]), "r"(a[1]), "r"(a[2]), "r"(a[3]), "r"(b[0]), "r"(b[1]));
}

__device__ __forceinline__ void ldsm_x4(unsigned& r0, unsigned& r1,
                                        unsigned& r2, unsigned& r3,
                                        unsigned addr) {
    asm volatile("ldmatrix.sync.aligned.m8n8.x4.shared.b16 {%0,%1,%2,%3}, [%4];"
                 : "=r"(r0), "=r"(r1), "=r"(r2), "=r"(r3) : "r"(addr));
}

__device__ __forceinline__ void cp_async16(void* smem, const void* gmem) {
    unsigned s = (unsigned)__cvta_generic_to_shared(smem);
    asm volatile("cp.async.cg.shared.global [%0], [%1], 16;\n" ::
                 "r"(s), "l"(gmem));
}
__device__ __forceinline__ void cp_commit() {
    asm volatile("cp.async.commit_group;\n");
}
template <int N>
__device__ __forceinline__ void cp_wait() {
    asm volatile("cp.async.wait_group %0;\n" :: "n"(N));
}

// ---------------------------------------------------------------------------
// Transpose + fp16 round: src[K][N] fp32 -> dst[N][K] fp16
// ---------------------------------------------------------------------------
__global__ void transpose_f16_k(const float* __restrict__ src,
                                __half* __restrict__ dst, int Kdim, int Ndim)
{
    __shared__ float t[32][33];
    int n0 = blockIdx.x * 32, k0 = blockIdx.y * 32;
    int tx = threadIdx.x, ty = threadIdx.y;
    #pragma unroll
    for (int i = 0; i < 4; i++)
        t[ty + i * 8][tx] =
            src[(size_t)(k0 + ty + i * 8) * Ndim + n0 + tx];
    __syncthreads();
    #pragma unroll
    for (int i = 0; i < 4; i++)
        dst[(size_t)(n0 + ty + i * 8) * Kdim + k0 + tx] =
            __float2half_rn(t[tx][ty + i * 8]);
}

// ---------------------------------------------------------------------------
// FP16 GEMM: ldmatrix fragments, 3-stage cp.async ring, one barrier/iter.
// A row-major [M][K] fp16, Bt row-major [N][K] fp16, fp32 accum/output.
// BM=256, BN=128, BK=64 (=128B rows), 256 thr (8 warps 4x2), warp 64x64.
// MODE 0: C[M,N] plain.  MODE 1: combined qkv|z epilogue with fused RoPE.
// ---------------------------------------------------------------------------
#define TSH 72                                 // halfs per smem row (144 B)
#define A_H (256 * TSH)                        // 18432 halfs
#define B_H (128 * TSH)                        // 9216 halfs
#define STAGE_H (A_H + B_H)                    // 27648
#define STAGE_BYTES (STAGE_H * 2)              // 55296
#define NSTAGE 3

template <int MODE>
__global__ __launch_bounds__(256, 1) void gemm_f16(
    const __half* __restrict__ A, const __half* __restrict__ Bt,
    float* __restrict__ C, int M, int N, int K)
{
    extern __shared__ __half sm[];
    const unsigned smem_u32 = (unsigned)__cvta_generic_to_shared(sm);

    const int tid  = threadIdx.x;
    const int wid  = tid >> 5;
    const int lane = tid & 31;
    const int r4   = lane >> 2;
    const int lc   = lane & 3;

    const int row0 = blockIdx.y * 256;
    const int col0 = blockIdx.x * 128;
    const int warp_row = (wid & 3) * 64;       // 0,64,128,192
    const int warp_col = (wid >> 2) * 64;      // 0 or 64

    auto issue = [&](int k0, int st) {
        __half* As = sm + st * STAGE_H;
        __half* Bs = As + A_H;
        #pragma unroll
        for (int i = 0; i < 8; i++) {          // A: 2048 chunks (256 rows)
            int idx = tid + i * 256;
            int r = idx >> 3, ch = idx & 7;
            cp_async16(&As[r * TSH + ch * 8],
                       &A[(size_t)(row0 + r) * K + k0 + ch * 8]);
        }
        #pragma unroll
        for (int i = 0; i < 4; i++) {          // B: 1024 chunks (128 rows)
            int idx = tid + i * 256;
            int r = idx >> 3, ch = idx & 7;
            cp_async16(&Bs[r * TSH + ch * 8],
                       &Bt[(size_t)(col0 + r) * K + k0 + ch * 8]);
        }
        cp_commit();
    };

    const int lrow = lane & 15;
    const int lcolb = (lane & 16) ? 16 : 0;    // byte offset (8 halfs)
    const unsigned a_lane = smem_u32 +
        (unsigned)((warp_row + lrow) * TSH * 2) + lcolb;
    const unsigned b_lane = smem_u32 + A_H * 2 +
        (unsigned)((warp_col + lrow) * TSH * 2) + lcolb;

    float c[4][8][4];
    #pragma unroll
    for (int i = 0; i < 4; i++)
        #pragma unroll
        for (int j = 0; j < 8; j++)
            #pragma unroll
            for (int t = 0; t < 4; t++) c[i][j][t] = 0.f;

    const int nk = K >> 6;                     // BK = 64
    issue(0, 0);
    issue(64, 1);

    #pragma unroll 1
    for (int t = 0; t < nk; t++) {
        if (t < nk - 1) cp_wait<1>(); else cp_wait<0>();
        __syncthreads();

        if (t + 2 < nk) issue((t + 2) << 6, (t + 2) % NSTAGE);

        const int cur = t % NSTAGE;
        const unsigned a_st = a_lane + cur * STAGE_BYTES;
        const unsigned b_st = b_lane + cur * STAGE_BYTES;
        #pragma unroll
        for (int kc = 0; kc < 4; kc++) {       // k16 per chunk
            const unsigned koff = kc * 32;     // 16 halfs = 32 bytes
            unsigned a[4][4], b[8][2];
            #pragma unroll
            for (int mt = 0; mt < 4; mt++)
                ldsm_x4(a[mt][0], a[mt][1], a[mt][2], a[mt][3],
                        a_st + (unsigned)(mt * 16 * TSH * 2) + koff);
            #pragma unroll
            for (int np = 0; np < 4; np++)
                ldsm_x4(b[2*np][0], b[2*np+1][0], b[2*np][1], b[2*np+1][1],
                        b_st + (unsigned)(np * 16 * TSH * 2) + koff);
            #pragma unroll
            for (int mt = 0; mt < 4; mt++)
                #pragma unroll
                for (int nt = 0; nt < 8; nt++)
                    mma_f16(c[mt][nt], a[mt], b[nt]);
        }
    }

    #pragma unroll
    for (int mt = 0; mt < 4; mt++) {
        #pragma unroll
        for (int nt = 0; nt < 8; nt++) {
            int rg = row0 + warp_row + mt * 16 + r4;
            int cg = col0 + warp_col + nt * 8 + 2 * lc;
            float v0 = c[mt][nt][0], v1 = c[mt][nt][1];
            float v2 = c[mt][nt][2], v3 = c[mt][nt][3];
            if (MODE == 1) {
                if (cg < 2 * KDD) {
                    int p = (cg & (DD - 1)) >> 1;
                    int pos0 = rg & (SS - 1);
                    int pos1 = (rg + 8) & (SS - 1);
                    float c0 = g_cos[pos0 * HALF_D + p], s0 = g_sin[pos0 * HALF_D + p];
                    float c1 = g_cos[pos1 * HALF_D + p], s1 = g_sin[pos1 * HALF_D + p];
                    float o0 = v0 * c0 - v1 * s0, o1 = v0 * s0 + v1 * c0;
                    float o2 = v2 * c1 - v3 * s1, o3 = v2 * s1 + v3 * c1;
                    v0 = o0; v1 = o1; v2 = o2; v3 = o3;
                }
                if (cg < 3 * KDD) {
                    *reinterpret_cast<float2*>(
                        &g_qkv[(size_t)rg * (3 * KDD) + cg]) = make_float2(v0, v1);
                    *reinterpret_cast<float2*>(
                        &g_qkv[(size_t)(rg + 8) * (3 * KDD) + cg]) = make_float2(v2, v3);
                } else {
                    int cz = cg - 3 * KDD;
                    *reinterpret_cast<float2*>(
                        &g_z[(size_t)rg * KDD + cz]) = make_float2(v0, v1);
                    *reinterpret_cast<float2*>(
                        &g_z[(size_t)(rg + 8) * KDD + cz]) = make_float2(v2, v3);
                }
            } else {
                *reinterpret_cast<float2*>(&C[(size_t)rg * N + cg]) =
                    make_float2(v0, v1);
                *reinterpret_cast<float2*>(&C[(size_t)(rg + 8) * N + cg]) =
                    make_float2(v2, v3);
            }
        }
    }
}

// ---------------------------------------------------------------------------
// Transpose Wb|Wa (HHx8 each) into g_Wt[16][HH]
// ---------------------------------------------------------------------------
__global__ void transpose_gates_k(const float* __restrict__ Wb,
                                  const float* __restrict__ Wa)
{
    int idx = blockIdx.x * blockDim.x + threadIdx.x;
    if (idx >= 16 * HH) return;
    int n = idx / HH, k = idx % HH;
    g_Wt[idx] = (n < 8) ? Wb[(size_t)k * NHH + n]
                        : Wa[(size_t)k * NHH + (n - 8)];
}

// ---------------------------------------------------------------------------
// Gate projections + x->fp16 emit: one block (512 thr) per row.
// ---------------------------------------------------------------------------
__global__ __launch_bounds__(512) void proj_gates2(const float* __restrict__ x)
{
    __shared__ float xs[HH];
    const int row = blockIdx.x;
    const float4 xv4 =
        reinterpret_cast<const float4*>(x + (size_t)row * HH)[threadIdx.x];
    reinterpret_cast<float4*>(xs)[threadIdx.x] = xv4;

    // emit fp16 x (4 elems per thread)
    {
        __half2 h0 = __floats2half2_rn(xv4.x, xv4.y);
        __half2 h1 = __floats2half2_rn(xv4.z, xv4.w);
        __half2* d = reinterpret_cast<__half2*>(
            g_xh + (size_t)row * HH + threadIdx.x * 4);
        d[0] = h0;
        d[1] = h1;
    }
    __syncthreads();

    const int w = threadIdx.x >> 5, lane = threadIdx.x & 31;
    const float* wt = g_Wt + w * HH;
    float s = 0.f;
    #pragma unroll
    for (int it = 0; it < HH / 128; it++) {
        int k = it * 128 + lane * 4;
        float4 xv = *reinterpret_cast<const float4*>(&xs[k]);
        float4 wv = *reinterpret_cast<const float4*>(&wt[k]);
        s += xv.x * wv.x + xv.y * wv.y + xv.z * wv.z + xv.w * wv.w;
    }
    #pragma unroll
    for (int o = 16; o > 0; o >>= 1) s += __shfl_down_sync(0xffffffffu, s, o);
    if (lane == 0) {
        if (w < 8) g_bg[(size_t)row * NHH + w] = s;
        else       g_ag[(size_t)row * NHH + (w - 8)] = s;
    }
}

// ---------------------------------------------------------------------------
// RoPE tables (fp32 angle, double inv-freq)
// ---------------------------------------------------------------------------
__global__ void rope_tables_k()
{
    int idx = blockIdx.x * blockDim.x + threadIdx.x;
    if (idx >= SS * HALF_D) return;
    int pos = idx / HALF_D, i = idx % HALF_D;
    float inv = (float)exp(-((double)(2 * i) / (double)DD) * log(1.0e6));
    float ang = (float)pos * inv;
    float s, c;
    sincosf(ang, &s, &c);
    g_cos[idx] = c;
    g_sin[idx] = s;
}

// ---------------------------------------------------------------------------
// Tiled sliding-window gated attention
// ---------------------------------------------------------------------------
#define ATS 32
__global__ __launch_bounds__(256) void attn2_k()
{
    __shared__ float ks[36 * DD];
    __shared__ float vs[36 * DD];
    __shared__ float bgs[36];
    __shared__ float ags[ATS];

    const int s_base = blockIdx.x * ATS;
    const int h = blockIdx.y, b = blockIdx.z;
    const int tid = threadIdx.x;
    const int wid = tid >> 5, lane = tid & 31;

    for (int t = tid; t < 36 * 32; t += 256) {
        int li = t >> 5, c4 = (t & 31) * 4;
        int j = s_base - 4 + li;
        float4 kv = make_float4(0.f, 0.f, 0.f, 0.f), vv = kv;
        if (j >= 0) {
            size_t r = (size_t)(b * SS + j) * (3 * KDD) + h * DD + c4;
            kv = *reinterpret_cast<const float4*>(&g_qkv[r + KDD]);
            vv = *reinterpret_cast<const float4*>(&g_qkv[r + 2 * KDD]);
        }
        *reinterpret_cast<float4*>(&ks[li * DD + c4]) = kv;
        *reinterpret_cast<float4*>(&vs[li * DD + c4]) = vv;
    }
    if (tid < 36) {
        int j = s_base - 4 + tid;
        bgs[tid] = (j >= 0) ? g_bg[(size_t)(b * SS + j) * NHH + h] : 0.f;
    }
    if (tid >= 64 && tid < 64 + ATS)
        ags[tid - 64] = g_ag[(size_t)(b * SS + s_base + tid - 64) * NHH + h];
    __syncthreads();

    const float scale = 0.08838834764831845f;

    #pragma unroll
    for (int i = 0; i < 4; i++) {
        const int sl = wid + 8 * i;
        const int s  = s_base + sl;
        const size_t orow = (size_t)(b * SS + s) * KDD + h * DD + lane * 4;

        if (s == 0) {
            *reinterpret_cast<float4*>(&g_att[orow]) =
                *reinterpret_cast<const float4*>(&vs[4 * DD + lane * 4]);
            continue;
        }

        const float4 q4 = *reinterpret_cast<const float4*>(
            &g_qkv[(size_t)(b * SS + s) * (3 * KDD) + h * DD + lane * 4]);
        const float agv = ags[sl];
        float4 acc = make_float4(0.f, 0.f, 0.f, 0.f);

        #pragma unroll
        for (int off = 0; off <= WW; off++) {
            if (s - off < 0) continue;
            const int li = sl + 4 - off;
            const float4 k4 = *reinterpret_cast<const float4*>(
                &ks[li * DD + lane * 4]);
            float part = q4.x * k4.x + q4.y * k4.y + q4.z * k4.z + q4.w * k4.w;
            #pragma unroll
            for (int o = 16; o > 0; o >>= 1)
                part += __shfl_xor_sync(0xffffffffu, part, o);
            const float gate = 1.f / (1.f + expf(-agv * bgs[li]));
            const float wgt = part * scale * gate;
            const float4 v4 = *reinterpret_cast<const float4*>(
                &vs[li * DD + lane * 4]);
            acc.x += wgt * v4.x; acc.y += wgt * v4.y;
            acc.z += wgt * v4.z; acc.w += wgt * v4.w;
        }
        *reinterpret_cast<float4*>(&g_att[orow]) = acc;
    }
}

// ---------------------------------------------------------------------------
// Gated RMS norm (emits fp16 yn)
// ---------------------------------------------------------------------------
__global__ __launch_bounds__(256) void norm_k(const float* __restrict__ nw)
{
    const int row = blockIdx.x, tid = threadIdx.x;
    const size_t base = (size_t)row * KDD;

    float y[4], zz[4];
    float ss = 0.f;
    #pragma unroll
    for (int i = 0; i < 4; i++) {
        int c   = tid + i * 256;
        float zv  = g_z[base + c];
        float sig = 1.f / (1.f + expf(-zv));
        float yv  = g_att[base + c] * sig;
        y[i]  = yv;
        zz[i] = zv * sig;
        ss   += yv * yv;
    }
    __shared__ float red[8];
    #pragma unroll
    for (int o = 16; o > 0; o >>= 1) ss += __shfl_down_sync(0xffffffffu, ss, o);
    if ((tid & 31) == 0) red[tid >> 5] = ss;
    __syncthreads();
    if (tid < 8) {
        float v = red[tid];
        #pragma unroll
        for (int o = 4; o > 0; o >>= 1) v += __shfl_down_sync(0xffu, v, o);
        if (tid == 0) red[0] = v;
    }
    __syncthreads();
    const float rinv = rsqrtf(red[0] / (float)KDD + 1e-6f);

    #pragma unroll
    for (int i = 0; i < 4; i++) {
        int c = tid + i * 256;
        g_ynh[base + c] = __float2half_rn(y[i] * rinv * nw[c] * zz[i]);
    }
}

// ---------------------------------------------------------------------------
// Launch
// ---------------------------------------------------------------------------
extern "C" void kernel_launch(void* const* d_in, const int* in_sizes, int n_in,
                              void* d_out, int out_size)
{
    const float* x    = (const float*)d_in[0];
    const float* Wqkv = (const float*)d_in[1];
    const float* Wz   = (const float*)d_in[2];
    const float* Wb   = (const float*)d_in[3];
    const float* Wa   = (const float*)d_in[4];
    const float* nw   = (const float*)d_in[5];
    const float* Wout = (const float*)d_in[6];
    float* out = (float*)d_out;

    __half *p_xh, *p_Wch, *p_Wouth, *p_ynh;
    cudaGetSymbolAddress((void**)&p_xh,    g_xh);
    cudaGetSymbolAddress((void**)&p_Wch,   g_Wch);
    cudaGetSymbolAddress((void**)&p_Wouth, g_Wouth);
    cudaGetSymbolAddress((void**)&p_ynh,   g_ynh);

    const int smem_bytes = NSTAGE * STAGE_BYTES;   // 165888
    static bool attr_set = false;
    if (!attr_set) {
        cudaFuncSetAttribute(gemm_f16<0>,
            cudaFuncAttributeMaxDynamicSharedMemorySize, smem_bytes);
        cudaFuncSetAttribute(gemm_f16<1>,
            cudaFuncAttributeMaxDynamicSharedMemorySize, smem_bytes);
        attr_set = true;
    }

    // 1) Gate weight transpose; gates + x->fp16; weight transposes; rope
    {
        int m = 16 * HH;
        transpose_gates_k<<<(m + 255) / 256, 256>>>(Wb, Wa);
        proj_gates2<<<MM, 512>>>(x);
        dim3 blk(32, 8);
        transpose_f16_k<<<dim3(3 * KDD / 32, HH / 32), blk>>>(
            Wqkv, p_Wch, HH, 3 * KDD);
        transpose_f16_k<<<dim3(KDD / 32, HH / 32), blk>>>(
            Wz, p_Wch + (size_t)3 * KDD * HH, HH, KDD);
        transpose_f16_k<<<dim3(HH / 32, KDD / 32), blk>>>(
            Wout, p_Wouth, KDD, HH);
        int t = SS * HALF_D;
        rope_tables_k<<<(t + 255) / 256, 256>>>();
    }

    // 2) Combined qkv|z projection (fp16 tensor cores, RoPE fused)
    {
        dim3 g(NCOMB / 128, MM / 256);
        gemm_f16<1><<<g, 256, smem_bytes>>>(p_xh, p_Wch, nullptr,
                                            MM, NCOMB, HH);
    }

    // 3) Tiled sliding-window gated attention
    {
        dim3 g(SS / ATS, NHH, BB);
        attn2_k<<<g, 256>>>();
    }

    // 4) Gated RMS norm (fp16 output)
    norm_k<<<MM, 256>>>(nw);

    // 5) Output projection (fp16 tensor cores)
    {
        dim3 g(HH / 128, MM / 256);
        gemm_f16<0><<<g, 256, smem_bytes>>>(p_ynh, p_Wouth, out, MM, HH, KDD);
    }
}

// round 17
// speedup vs baseline: 1.8268x; 1.0941x over previous
#include <cuda_runtime.h>
#include <cuda_fp16.h>
#include <math.h>

// Problem constants
#define BB  2
#define SS  4096
#define HH  2048
#define NHH 8
#define DD  128
#define KDD 1024        // NH*D
#define WW  4
#define MM  (BB*SS)     // 8192
#define HALF_D 64
#define NCOMB2 (4 * KDD + 128) // 4224 = qkv(3072) + z(1024) + gates(16)+pad

// ---------------------------------------------------------------------------
// Device scratch
// ---------------------------------------------------------------------------
__device__ float g_qkv[(size_t)MM * 3 * KDD];
__device__ float g_z  [(size_t)MM * KDD];
__device__ float g_bg [(size_t)MM * NHH];
__device__ float g_ag [(size_t)MM * NHH];
__device__ float g_att[(size_t)MM * KDD];
__device__ float g_cos[(size_t)SS * HALF_D];
__device__ float g_sin[(size_t)SS * HALF_D];
__device__ __half g_xh  [(size_t)MM * HH];       // fp16 x
__device__ __half g_Wch [(size_t)NCOMB2 * HH];   // [Wqkv^T|Wz^T|Wb,Wa^T|pad]
__device__ __half g_Wouth[(size_t)HH * KDD];     // Wout^T fp16 [HH][KDD]
__device__ __half g_ynh [(size_t)MM * KDD];      // fp16 normed y

// ---------------------------------------------------------------------------
// helpers
// ---------------------------------------------------------------------------
__device__ __forceinline__ void mma_f16(float c[4], const unsigned a[4],
                                        const unsigned b[2]) {
    asm volatile(
        "mma.sync.aligned.m16n8k16.row.col.f32.f16.f16.f32 "
        "{%0,%1,%2,%3}, {%4,%5,%6,%7}, {%8,%9}, {%0,%1,%2,%3};"
        : "+f"(c[0]), "+f"(c[1]), "+f"(c[2]), "+f"(c[3])
        : "r"(a[0]), "r"(a[1]), "r"(a[2]), "r"(a[3]), "r"(b[0]), "r"(b[1]));
}

__device__ __forceinline__ void ldsm_x4(unsigned& r0, unsigned& r1,
                                        unsigned& r2, unsigned& r3,
                                        unsigned addr) {
    asm volatile("ldmatrix.sync.aligned.m8n8.x4.shared.b16 {%0,%1,%2,%3}, [%4];"
                 : "=r"(r0), "=r"(r1), "=r"(r2), "=r"(r3) : "r"(addr));
}

__device__ __forceinline__ void cp_async16(void* smem, const void* gmem) {
    unsigned s = (unsigned)__cvta_generic_to_shared(smem);
    asm volatile("cp.async.cg.shared.global [%0], [%1], 16;\n" ::
                 "r"(s), "l"(gmem));
}
__device__ __forceinline__ void cp_commit() {
    asm volatile("cp.async.commit_group;\n");
}
template <int N>
__device__ __forceinline__ void cp_wait() {
    asm volatile("cp.async.wait_group %0;\n" :: "n"(N));
}

// ---------------------------------------------------------------------------
// x -> fp16 (float4 per thread)
// ---------------------------------------------------------------------------
__global__ void round_f16_k(const float* __restrict__ src,
                            __half* __restrict__ dst, int n4)
{
    int i = blockIdx.x * blockDim.x + threadIdx.x;
    if (i >= n4) return;
    float4 v = reinterpret_cast<const float4*>(src)[i];
    __half2 h0 = __floats2half2_rn(v.x, v.y);
    __half2 h1 = __floats2half2_rn(v.z, v.w);
    __half2* d = reinterpret_cast<__half2*>(dst + (size_t)i * 4);
    d[0] = h0;
    d[1] = h1;
}

// ---------------------------------------------------------------------------
// Transpose + fp16 round: src[K][N] fp32 -> dst[N][K] fp16
// ---------------------------------------------------------------------------
__global__ void transpose_f16_k(const float* __restrict__ src,
                                __half* __restrict__ dst, int Kdim, int Ndim)
{
    __shared__ float t[32][33];
    int n0 = blockIdx.x * 32, k0 = blockIdx.y * 32;
    int tx = threadIdx.x, ty = threadIdx.y;
    #pragma unroll
    for (int i = 0; i < 4; i++)
        t[ty + i * 8][tx] =
            src[(size_t)(k0 + ty + i * 8) * Ndim + n0 + tx];
    __syncthreads();
    #pragma unroll
    for (int i = 0; i < 4; i++)
        dst[(size_t)(n0 + ty + i * 8) * Kdim + k0 + tx] =
            __float2half_rn(t[tx][ty + i * 8]);
}

// ---------------------------------------------------------------------------
// Transpose Wb|Wa (HHx8 each) into g_Wch rows [4096..4112) as fp16
// ---------------------------------------------------------------------------
__global__ void transpose_gates_f16_k(const float* __restrict__ Wb,
                                      const float* __restrict__ Wa)
{
    int idx = blockIdx.x * blockDim.x + threadIdx.x;
    if (idx >= 16 * HH) return;
    int n = idx / HH, k = idx % HH;
    float v = (n < 8) ? Wb[(size_t)k * NHH + n]
                      : Wa[(size_t)k * NHH + (n - 8)];
    g_Wch[(size_t)(4 * KDD + n) * HH + k] = __float2half_rn(v);
}

// ---------------------------------------------------------------------------
// FP16 GEMM: ldmatrix fragments, 3-stage cp.async ring, one barrier/iter.
// A row-major [M][K] fp16, Bt row-major [N][K] fp16, fp32 accum/output.
// BM=256, BN=128, BK=64 (=128B rows), 256 thr (8 warps 4x2), warp 64x64.
// MODE 0: C[M,N] plain.
// MODE 1: combined epilogue: cols <3KDD -> qkv (RoPE on <2KDD),
//         <4KDD -> z, [4KDD,4KDD+16) -> bg|ag, rest discarded.
// ---------------------------------------------------------------------------
#define TSH 72                                 // halfs per smem row (144 B)
#define A_H (256 * TSH)                        // 18432 halfs
#define B_H (128 * TSH)                        // 9216 halfs
#define STAGE_H (A_H + B_H)                    // 27648
#define STAGE_BYTES (STAGE_H * 2)              // 55296
#define NSTAGE 3

template <int MODE>
__global__ __launch_bounds__(256, 1) void gemm_f16(
    const __half* __restrict__ A, const __half* __restrict__ Bt,
    float* __restrict__ C, int M, int N, int K)
{
    extern __shared__ __half sm[];
    const unsigned smem_u32 = (unsigned)__cvta_generic_to_shared(sm);

    const int tid  = threadIdx.x;
    const int wid  = tid >> 5;
    const int lane = tid & 31;
    const int r4   = lane >> 2;
    const int lc   = lane & 3;

    const int row0 = blockIdx.y * 256;
    const int col0 = blockIdx.x * 128;
    const int warp_row = (wid & 3) * 64;       // 0,64,128,192
    const int warp_col = (wid >> 2) * 64;      // 0 or 64

    auto issue = [&](int k0, int st) {
        __half* As = sm + st * STAGE_H;
        __half* Bs = As + A_H;
        #pragma unroll
        for (int i = 0; i < 8; i++) {          // A: 2048 chunks (256 rows)
            int idx = tid + i * 256;
            int r = idx >> 3, ch = idx & 7;
            cp_async16(&As[r * TSH + ch * 8],
                       &A[(size_t)(row0 + r) * K + k0 + ch * 8]);
        }
        #pragma unroll
        for (int i = 0; i < 4; i++) {          // B: 1024 chunks (128 rows)
            int idx = tid + i * 256;
            int r = idx >> 3, ch = idx & 7;
            cp_async16(&Bs[r * TSH + ch * 8],
                       &Bt[(size_t)(col0 + r) * K + k0 + ch * 8]);
        }
        cp_commit();
    };

    const int lrow = lane & 15;
    const int lcolb = (lane & 16) ? 16 : 0;    // byte offset (8 halfs)
    const unsigned a_lane = smem_u32 +
        (unsigned)((warp_row + lrow) * TSH * 2) + lcolb;
    const unsigned b_lane = smem_u32 + A_H * 2 +
        (unsigned)((warp_col + lrow) * TSH * 2) + lcolb;

    float c[4][8][4];
    #pragma unroll
    for (int i = 0; i < 4; i++)
        #pragma unroll
        for (int j = 0; j < 8; j++)
            #pragma unroll
            for (int t = 0; t < 4; t++) c[i][j][t] = 0.f;

    const int nk = K >> 6;                     // BK = 64
    issue(0, 0);
    issue(64, 1);

    #pragma unroll 1
    for (int t = 0; t < nk; t++) {
        if (t < nk - 1) cp_wait<1>(); else cp_wait<0>();
        __syncthreads();

        if (t + 2 < nk) issue((t + 2) << 6, (t + 2) % NSTAGE);

        const int cur = t % NSTAGE;
        const unsigned a_st = a_lane + cur * STAGE_BYTES;
        const unsigned b_st = b_lane + cur * STAGE_BYTES;
        #pragma unroll
        for (int kc = 0; kc < 4; kc++) {       // k16 per chunk
            const unsigned koff = kc * 32;     // 16 halfs = 32 bytes
            unsigned a[4][4], b[8][2];
            #pragma unroll
            for (int mt = 0; mt < 4; mt++)
                ldsm_x4(a[mt][0], a[mt][1], a[mt][2], a[mt][3],
                        a_st + (unsigned)(mt * 16 * TSH * 2) + koff);
            #pragma unroll
            for (int np = 0; np < 4; np++)
                ldsm_x4(b[2*np][0], b[2*np+1][0], b[2*np][1], b[2*np+1][1],
                        b_st + (unsigned)(np * 16 * TSH * 2) + koff);
            #pragma unroll
            for (int mt = 0; mt < 4; mt++)
                #pragma unroll
                for (int nt = 0; nt < 8; nt++)
                    mma_f16(c[mt][nt], a[mt], b[nt]);
        }
    }

    #pragma unroll
    for (int mt = 0; mt < 4; mt++) {
        #pragma unroll
        for (int nt = 0; nt < 8; nt++) {
            int rg = row0 + warp_row + mt * 16 + r4;
            int cg = col0 + warp_col + nt * 8 + 2 * lc;
            float v0 = c[mt][nt][0], v1 = c[mt][nt][1];
            float v2 = c[mt][nt][2], v3 = c[mt][nt][3];
            if (MODE == 1) {
                if (cg < 2 * KDD) {
                    int p = (cg & (DD - 1)) >> 1;
                    int pos0 = rg & (SS - 1);
                    int pos1 = (rg + 8) & (SS - 1);
                    float c0 = g_cos[pos0 * HALF_D + p], s0 = g_sin[pos0 * HALF_D + p];
                    float c1 = g_cos[pos1 * HALF_D + p], s1 = g_sin[pos1 * HALF_D + p];
                    float o0 = v0 * c0 - v1 * s0, o1 = v0 * s0 + v1 * c0;
                    float o2 = v2 * c1 - v3 * s1, o3 = v2 * s1 + v3 * c1;
                    v0 = o0; v1 = o1; v2 = o2; v3 = o3;
                }
                if (cg < 3 * KDD) {
                    *reinterpret_cast<float2*>(
                        &g_qkv[(size_t)rg * (3 * KDD) + cg]) = make_float2(v0, v1);
                    *reinterpret_cast<float2*>(
                        &g_qkv[(size_t)(rg + 8) * (3 * KDD) + cg]) = make_float2(v2, v3);
                } else if (cg < 4 * KDD) {
                    int cz = cg - 3 * KDD;
                    *reinterpret_cast<float2*>(
                        &g_z[(size_t)rg * KDD + cz]) = make_float2(v0, v1);
                    *reinterpret_cast<float2*>(
                        &g_z[(size_t)(rg + 8) * KDD + cz]) = make_float2(v2, v3);
                } else {
                    int n = cg - 4 * KDD;      // even; pairs (n, n+1)
                    if (n < 16) {
                        float* d0 = (n < 8) ? &g_bg[(size_t)rg * NHH + n]
                                            : &g_ag[(size_t)rg * NHH + n - 8];
                        d0[0] = v0;
                        if (n + 1 < 8 || (n >= 8 && n + 1 < 16)) d0[1] = v1;
                        float* d2 = (n < 8) ? &g_bg[(size_t)(rg + 8) * NHH + n]
                                            : &g_ag[(size_t)(rg + 8) * NHH + n - 8];
                        d2[0] = v2;
                        if (n + 1 < 8 || (n >= 8 && n + 1 < 16)) d2[1] = v3;
                    }
                }
            } else {
                *reinterpret_cast<float2*>(&C[(size_t)rg * N + cg]) =
                    make_float2(v0, v1);
                *reinterpret_cast<float2*>(&C[(size_t)(rg + 8) * N + cg]) =
                    make_float2(v2, v3);
            }
        }
    }
}

// ---------------------------------------------------------------------------
// RoPE tables (fp32 angle, double inv-freq)
// ---------------------------------------------------------------------------
__global__ void rope_tables_k()
{
    int idx = blockIdx.x * blockDim.x + threadIdx.x;
    if (idx >= SS * HALF_D) return;
    int pos = idx / HALF_D, i = idx % HALF_D;
    float inv = (float)exp(-((double)(2 * i) / (double)DD) * log(1.0e6));
    float ang = (float)pos * inv;
    float s, c;
    sincosf(ang, &s, &c);
    g_cos[idx] = c;
    g_sin[idx] = s;
}

// ---------------------------------------------------------------------------
// Tiled sliding-window gated attention
// ---------------------------------------------------------------------------
#define ATS 32
__global__ __launch_bounds__(256) void attn2_k()
{
    __shared__ float ks[36 * DD];
    __shared__ float vs[36 * DD];
    __shared__ float bgs[36];
    __shared__ float ags[ATS];

    const int s_base = blockIdx.x * ATS;
    const int h = blockIdx.y, b = blockIdx.z;
    const int tid = threadIdx.x;
    const int wid = tid >> 5, lane = tid & 31;

    for (int t = tid; t < 36 * 32; t += 256) {
        int li = t >> 5, c4 = (t & 31) * 4;
        int j = s_base - 4 + li;
        float4 kv = make_float4(0.f, 0.f, 0.f, 0.f), vv = kv;
        if (j >= 0) {
            size_t r = (size_t)(b * SS + j) * (3 * KDD) + h * DD + c4;
            kv = *reinterpret_cast<const float4*>(&g_qkv[r + KDD]);
            vv = *reinterpret_cast<const float4*>(&g_qkv[r + 2 * KDD]);
        }
        *reinterpret_cast<float4*>(&ks[li * DD + c4]) = kv;
        *reinterpret_cast<float4*>(&vs[li * DD + c4]) = vv;
    }
    if (tid < 36) {
        int j = s_base - 4 + tid;
        bgs[tid] = (j >= 0) ? g_bg[(size_t)(b * SS + j) * NHH + h] : 0.f;
    }
    if (tid >= 64 && tid < 64 + ATS)
        ags[tid - 64] = g_ag[(size_t)(b * SS + s_base + tid - 64) * NHH + h];
    __syncthreads();

    const float scale = 0.08838834764831845f;

    #pragma unroll
    for (int i = 0; i < 4; i++) {
        const int sl = wid + 8 * i;
        const int s  = s_base + sl;
        const size_t orow = (size_t)(b * SS + s) * KDD + h * DD + lane * 4;

        if (s == 0) {
            *reinterpret_cast<float4*>(&g_att[orow]) =
                *reinterpret_cast<const float4*>(&vs[4 * DD + lane * 4]);
            continue;
        }

        const float4 q4 = *reinterpret_cast<const float4*>(
            &g_qkv[(size_t)(b * SS + s) * (3 * KDD) + h * DD + lane * 4]);
        const float agv = ags[sl];
        float4 acc = make_float4(0.f, 0.f, 0.f, 0.f);

        #pragma unroll
        for (int off = 0; off <= WW; off++) {
            if (s - off < 0) continue;
            const int li = sl + 4 - off;
            const float4 k4 = *reinterpret_cast<const float4*>(
                &ks[li * DD + lane * 4]);
            float part = q4.x * k4.x + q4.y * k4.y + q4.z * k4.z + q4.w * k4.w;
            #pragma unroll
            for (int o = 16; o > 0; o >>= 1)
                part += __shfl_xor_sync(0xffffffffu, part, o);
            const float gate = 1.f / (1.f + expf(-agv * bgs[li]));
            const float wgt = part * scale * gate;
            const float4 v4 = *reinterpret_cast<const float4*>(
                &vs[li * DD + lane * 4]);
            acc.x += wgt * v4.x; acc.y += wgt * v4.y;
            acc.z += wgt * v4.z; acc.w += wgt * v4.w;
        }
        *reinterpret_cast<float4*>(&g_att[orow]) = acc;
    }
}

// ---------------------------------------------------------------------------
// Gated RMS norm (emits fp16 yn)
// ---------------------------------------------------------------------------
__global__ __launch_bounds__(256) void norm_k(const float* __restrict__ nw)
{
    const int row = blockIdx.x, tid = threadIdx.x;
    const size_t base = (size_t)row * KDD;

    float y[4], zz[4];
    float ss = 0.f;
    #pragma unroll
    for (int i = 0; i < 4; i++) {
        int c   = tid + i * 256;
        float zv  = g_z[base + c];
        float sig = 1.f / (1.f + expf(-zv));
        float yv  = g_att[base + c] * sig;
        y[i]  = yv;
        zz[i] = zv * sig;
        ss   += yv * yv;
    }
    __shared__ float red[8];
    #pragma unroll
    for (int o = 16; o > 0; o >>= 1) ss += __shfl_down_sync(0xffffffffu, ss, o);
    if ((tid & 31) == 0) red[tid >> 5] = ss;
    __syncthreads();
    if (tid < 8) {
        float v = red[tid];
        #pragma unroll
        for (int o = 4; o > 0; o >>= 1) v += __shfl_down_sync(0xffu, v, o);
        if (tid == 0) red[0] = v;
    }
    __syncthreads();
    const float rinv = rsqrtf(red[0] / (float)KDD + 1e-6f);

    #pragma unroll
    for (int i = 0; i < 4; i++) {
        int c = tid + i * 256;
        g_ynh[base + c] = __float2half_rn(y[i] * rinv * nw[c] * zz[i]);
    }
}

// ---------------------------------------------------------------------------
// Launch
// ---------------------------------------------------------------------------
extern "C" void kernel_launch(void* const* d_in, const int* in_sizes, int n_in,
                              void* d_out, int out_size)
{
    const float* x    = (const float*)d_in[0];
    const float* Wqkv = (const float*)d_in[1];
    const float* Wz   = (const float*)d_in[2];
    const float* Wb   = (const float*)d_in[3];
    const float* Wa   = (const float*)d_in[4];
    const float* nw   = (const float*)d_in[5];
    const float* Wout = (const float*)d_in[6];
    float* out = (float*)d_out;

    __half *p_xh, *p_Wch, *p_Wouth, *p_ynh;
    cudaGetSymbolAddress((void**)&p_xh,    g_xh);
    cudaGetSymbolAddress((void**)&p_Wch,   g_Wch);
    cudaGetSymbolAddress((void**)&p_Wouth, g_Wouth);
    cudaGetSymbolAddress((void**)&p_ynh,   g_ynh);

    const int smem_bytes = NSTAGE * STAGE_BYTES;   // 165888
    static bool attr_set = false;
    if (!attr_set) {
        cudaFuncSetAttribute(gemm_f16<0>,
            cudaFuncAttributeMaxDynamicSharedMemorySize, smem_bytes);
        cudaFuncSetAttribute(gemm_f16<1>,
            cudaFuncAttributeMaxDynamicSharedMemorySize, smem_bytes);
        attr_set = true;
    }

    // 1) x->fp16; weight transposes (incl. gates); rope tables
    {
        int n = MM * HH / 4;
        round_f16_k<<<(n + 255) / 256, 256>>>(x, p_xh, n);
        dim3 blk(32, 8);
        transpose_f16_k<<<dim3(3 * KDD / 32, HH / 32), blk>>>(
            Wqkv, p_Wch, HH, 3 * KDD);
        transpose_f16_k<<<dim3(KDD / 32, HH / 32), blk>>>(
            Wz, p_Wch + (size_t)3 * KDD * HH, HH, KDD);
        transpose_f16_k<<<dim3(HH / 32, KDD / 32), blk>>>(
            Wout, p_Wouth, KDD, HH);
        int m = 16 * HH;
        transpose_gates_f16_k<<<(m + 255) / 256, 256>>>(Wb, Wa);
        int t = SS * HALF_D;
        rope_tables_k<<<(t + 255) / 256, 256>>>();
    }

    // 2) Combined qkv|z|gates projection (fp16 tensor cores, RoPE fused)
    {
        dim3 g(NCOMB2 / 128, MM / 256);
        gemm_f16<1><<<g, 256, smem_bytes>>>(p_xh, p_Wch, nullptr,
                                            MM, NCOMB2, HH);
    }

    // 3) Tiled sliding-window gated attention
    {
        dim3 g(SS / ATS, NHH, BB);
        attn2_k<<<g, 256>>>();
    }

    // 4) Gated RMS norm (fp16 output)
    norm_k<<<MM, 256>>>(nw);

    // 5) Output projection (fp16 tensor cores)
    {
        dim3 g(HH / 128, MM / 256);
        gemm_f16<0><<<g, 256, smem_bytes>>>(p_ynh, p_Wouth, out, MM, HH, KDD);
    }
}